// round 14
// baseline (speedup 1.0000x reference)
#include <cuda_runtime.h>
#include <cuda_bf16.h>
#include <cuda_fp16.h>
#include <cstdint>

#define S_LEN 4096
#define NHEAD 16
#define HD    64
#define WIN   128
#define QT    64
#define KT    64
#define NKT   5        // (QT + 2*WIN) / KT

// ---- static smem byte offsets (tiles: 64 rows x 128 bytes, XOR-swizzled) ----
#define SM_Q   0
#define SM_K   8192
#define SM_V   16384
#define SM_TOTAL 24576

// 0.125 * log2(e)
#define QSCALE 0.1803368801111204f
#define ONES_H2 0x3C003C00u

__device__ __forceinline__ uint32_t swz(uint32_t o) {
    return o ^ (((o >> 7) & 7u) << 4);
}
__device__ __forceinline__ uint32_t smem_u32(const void* p) {
    uint32_t a;
    asm("{ .reg .u64 t; cvta.to.shared.u64 t, %1; cvt.u32.u64 %0, t; }" : "=r"(a) : "l"(p));
    return a;
}
__device__ __forceinline__ void ldsm4(uint32_t addr, uint32_t* r) {
    asm volatile("ldmatrix.sync.aligned.m8n8.x4.shared.b16 {%0,%1,%2,%3}, [%4];"
        : "=r"(r[0]), "=r"(r[1]), "=r"(r[2]), "=r"(r[3]) : "r"(addr));
}
__device__ __forceinline__ void ldsm4t(uint32_t addr, uint32_t* r) {
    asm volatile("ldmatrix.sync.aligned.m8n8.x4.trans.shared.b16 {%0,%1,%2,%3}, [%4];"
        : "=r"(r[0]), "=r"(r[1]), "=r"(r[2]), "=r"(r[3]) : "r"(addr));
}
__device__ __forceinline__ void mma_f16(float* c, const uint32_t* a, uint32_t b0, uint32_t b1) {
    asm volatile("mma.sync.aligned.m16n8k16.row.col.f32.f16.f16.f32 "
        "{%0,%1,%2,%3}, {%4,%5,%6,%7}, {%8,%9}, {%0,%1,%2,%3};"
        : "+f"(c[0]), "+f"(c[1]), "+f"(c[2]), "+f"(c[3])
        : "r"(a[0]), "r"(a[1]), "r"(a[2]), "r"(a[3]), "r"(b0), "r"(b1));
}
__device__ __forceinline__ uint32_t pack_h2(float lo, float hi) {
    __half2 h = __floats2half2_rn(lo, hi);
    return *reinterpret_cast<uint32_t*>(&h);
}
__device__ __forceinline__ float ex2(float x) {
    float r;
    asm("ex2.approx.f32 %0, %1;" : "=f"(r) : "f"(x));
    return r;
}

__global__ void __launch_bounds__(128, 4)
wattn_mma_kernel(const float* __restrict__ Q, const float* __restrict__ K,
                 const float* __restrict__ V, float* __restrict__ O) {
    __shared__ char smem[SM_TOTAL];
    const uint32_t sb = smem_u32(smem);

    const int tid  = threadIdx.x;
    const int wid  = tid >> 5;
    const int lane = tid & 31;

    const int q0 = blockIdx.x * QT;
    const int b  = blockIdx.y >> 4;
    const int n  = blockIdx.y & 15;
    const size_t base = ((size_t)b * S_LEN * NHEAD + (size_t)n) * (size_t)HD;
    const int rs = NHEAD * HD;

    const int pc4 = tid & 15;        // dim-quad 0..15 (4 dims = 8 bytes)
    const int r0  = tid >> 4;        // row base 0..7

    // ---- load Q tile -> fp16, swizzled [row][dim], scaled by 0.125*log2e ----
    {
        #pragma unroll
        for (int i = 0; i < 8; i++) {
            const int r = r0 + i * 8;
            const float4 x = *(const float4*)(Q + base + (size_t)(q0 + r) * rs + pc4 * 4);
            const uint32_t off = swz((uint32_t)(r * 128 + pc4 * 8));
            *(uint2*)(smem + SM_Q + off) =
                make_uint2(pack_h2(x.x * QSCALE, x.y * QSCALE),
                           pack_h2(x.z * QSCALE, x.w * QSCALE));
        }
    }

    const int g = lane >> 2;
    const int t = lane & 3;
    const int gq0 = q0 + wid * 16 + g;
    const int gq1 = gq0 + 8;
    const int wlo0 = (gq0 - WIN) > 0 ? (gq0 - WIN) : 0;
    const int whi0 = (gq0 + WIN) < (S_LEN - 1) ? (gq0 + WIN) : (S_LEN - 1);
    const int wlo1 = (gq1 - WIN) > 0 ? (gq1 - WIN) : 0;
    const int whi1 = (gq1 + WIN) < (S_LEN - 1) ? (gq1 + WIN) : (S_LEN - 1);
    const uint32_t rng0 = (uint32_t)(whi0 - wlo0);
    const uint32_t rng1 = (uint32_t)(whi1 - wlo1);

    float oc[8][4];
    #pragma unroll
    for (int i = 0; i < 8; i++)
        #pragma unroll
        for (int j = 0; j < 4; j++) oc[i][j] = 0.0f;
    float lsc[4] = {0.0f, 0.0f, 0.0f, 0.0f};   // row-sum c-frag

    // ldmatrix addressing (lane-dependent, loop-invariant)
    const int qa_row  = wid * 16 + (lane & 15);
    const int qa_dsel = ((lane >> 4) & 1) * 16;
    const int kb_key  = (lane & 7) + ((lane & 16) ? 8 : 0);
    const int kb_dsel = (lane & 8) ? 16 : 0;
    const int vb_key  = (lane & 7) + ((lane & 8) ? 8 : 0);
    const int vb_dsel = (lane & 16) ? 16 : 0;

    for (int kt = 0; kt < NKT; kt++) {
        const int kbase = q0 - WIN + kt * KT;
        const int kt4 = kt * 4;      // 16-key group base index

        __syncthreads();

        // ---- load K (fp16) and V (fp16) tiles, swizzled [key][dim] ----
        #pragma unroll
        for (int i = 0; i < 8; i++) {
            const int r = r0 + i * 8;
            const int gk = kbase + r;
            float4 xk = make_float4(0.f, 0.f, 0.f, 0.f);
            float4 xv = make_float4(0.f, 0.f, 0.f, 0.f);
            if (gk >= 0 && gk < S_LEN) {
                xk = *(const float4*)(K + base + (size_t)gk * rs + pc4 * 4);
                xv = *(const float4*)(V + base + (size_t)gk * rs + pc4 * 4);
            }
            const uint32_t off = swz((uint32_t)(r * 128 + pc4 * 8));
            *(uint2*)(smem + SM_K + off) =
                make_uint2(pack_h2(xk.x, xk.y), pack_h2(xk.z, xk.w));
            *(uint2*)(smem + SM_V + off) =
                make_uint2(pack_h2(xv.x, xv.y), pack_h2(xv.z, xv.w));
        }
        __syncthreads();

        // ---- QK^T: S[16q x 64k], single-term fp16, group skip ----
        float sc[8][4];
        #pragma unroll
        for (int i = 0; i < 8; i++)
            #pragma unroll
            for (int j = 0; j < 4; j++) sc[i][j] = 0.0f;

        #pragma unroll
        for (int ks = 0; ks < 4; ks++) {
            uint32_t qh[4];
            const uint32_t qoff = swz((uint32_t)(qa_row * 128 + ks * 32 + qa_dsel));
            ldsm4(sb + SM_Q + qoff, qh);
            #pragma unroll
            for (int ng = 0; ng < 4; ng++) {
                const int g16 = kt4 + ng;
                if (g16 < wid || g16 > wid + 16) continue;   // warp-uniform skip
                const uint32_t off = swz((uint32_t)((ng * 16 + kb_key) * 128 + ks * 32 + kb_dsel));
                uint32_t bh[4];
                ldsm4(sb + SM_K + off, bh);
                mma_f16(sc[2 * ng],     qh, bh[0], bh[1]);
                mma_f16(sc[2 * ng + 1], qh, bh[2], bh[3]);
            }
        }

        // ---- per 16-key group: mask + exp2 + pack P(fp16) + lsum-MMA + PV ----
        const int klo0 = wlo0 - kbase;
        const int klo1 = wlo1 - kbase;
        #pragma unroll
        for (int s = 0; s < 4; s++) {
            const int g16 = kt4 + s;
            if (g16 < wid || g16 > wid + 16) continue;       // warp-uniform skip

            // interior groups: every row's window provably covers all 16 keys
            const int kb16 = kbase + s * 16;
            const bool noMask = (g16 > wid) && (g16 < wid + 16) &&
                                (kb16 >= 0) && (kb16 + 16 <= S_LEN);
            float p[8];
            if (noMask) {
                p[0] = ex2(sc[2*s][0]);   p[1] = ex2(sc[2*s][1]);
                p[2] = ex2(sc[2*s][2]);   p[3] = ex2(sc[2*s][3]);
                p[4] = ex2(sc[2*s+1][0]); p[5] = ex2(sc[2*s+1][1]);
                p[6] = ex2(sc[2*s+1][2]); p[7] = ex2(sc[2*s+1][3]);
            } else {
                const int ia = s * 16 + 2 * t;
                const int ib = ia + 8;
                p[0] = ((uint32_t)(ia - klo0)     <= rng0) ? ex2(sc[2*s][0])   : 0.0f;
                p[1] = ((uint32_t)(ia + 1 - klo0) <= rng0) ? ex2(sc[2*s][1])   : 0.0f;
                p[2] = ((uint32_t)(ia - klo1)     <= rng1) ? ex2(sc[2*s][2])   : 0.0f;
                p[3] = ((uint32_t)(ia + 1 - klo1) <= rng1) ? ex2(sc[2*s][3])   : 0.0f;
                p[4] = ((uint32_t)(ib - klo0)     <= rng0) ? ex2(sc[2*s+1][0]) : 0.0f;
                p[5] = ((uint32_t)(ib + 1 - klo0) <= rng0) ? ex2(sc[2*s+1][1]) : 0.0f;
                p[6] = ((uint32_t)(ib - klo1)     <= rng1) ? ex2(sc[2*s+1][2]) : 0.0f;
                p[7] = ((uint32_t)(ib + 1 - klo1) <= rng1) ? ex2(sc[2*s+1][3]) : 0.0f;
            }

            uint32_t phi[4];
            phi[0] = pack_h2(p[0], p[1]);
            phi[1] = pack_h2(p[2], p[3]);
            phi[2] = pack_h2(p[4], p[5]);
            phi[3] = pack_h2(p[6], p[7]);

            mma_f16(lsc, phi, ONES_H2, ONES_H2);   // row sums via ones-B

            #pragma unroll
            for (int dg = 0; dg < 4; dg++) {
                const uint32_t off = swz((uint32_t)((s * 16 + vb_key) * 128 + dg * 32 + vb_dsel));
                uint32_t vh[4];
                ldsm4t(sb + SM_V + off, vh);
                mma_f16(oc[2 * dg],     phi, vh[0], vh[1]);
                mma_f16(oc[2 * dg + 1], phi, vh[2], vh[3]);
            }
        }
    }

    const float inv0 = 1.0f / lsc[0];
    const float inv1 = 1.0f / lsc[2];

    // ---- write output: O[b][gq][n][d] ----
    float* dst0 = O + base + (size_t)gq0 * rs;
    float* dst1 = O + base + (size_t)gq1 * rs;
    #pragma unroll
    for (int nt = 0; nt < 8; nt++) {
        const int d = nt * 8 + 2 * t;
        *(float2*)(dst0 + d) = make_float2(oc[nt][0] * inv0, oc[nt][1] * inv0);
        *(float2*)(dst1 + d) = make_float2(oc[nt][2] * inv1, oc[nt][3] * inv1);
    }
}

extern "C" void kernel_launch(void* const* d_in, const int* in_sizes, int n_in,
                              void* d_out, int out_size) {
    const float* q = (const float*)d_in[0];
    const float* k = (const float*)d_in[1];
    const float* v = (const float*)d_in[2];
    float* out = (float*)d_out;

    const int b = in_sizes[0] / (S_LEN * NHEAD * HD);

    dim3 grid(S_LEN / QT, b * NHEAD);
    wattn_mma_kernel<<<grid, 128>>>(q, k, v, out);
}